// round 10
// baseline (speedup 1.0000x reference)
#include <cuda_runtime.h>
#include <cstdint>

#define Bn   128
#define Tn   50
#define MI   32
#define En   128
#define Dn   144
#define G3   432
#define KD   144
#define KH   72           // GEMM k-slab
#define KP2  76           // padded slab stride (floats)
#define GTHR 216          // GRU threads: 2 gate-rows per thread

typedef unsigned long long ull;

__device__ float g_seq [Bn*Tn*Dn];
__device__ float g_gi  [Bn*Tn*G3];
__device__ float g_hseq[Bn*Tn*Dn];

// ---- f32x2 helpers ---------------------------------------------------------
__device__ __forceinline__ void fma2(ull& d, ull a, ull b) {
    asm("fma.rn.f32x2 %0, %1, %2, %0;" : "+l"(d) : "l"(a), "l"(b));
}
__device__ __forceinline__ float hsum2(ull v) {
    float lo, hi;
    asm("mov.b64 {%0,%1}, %2;" : "=f"(lo), "=f"(hi) : "l"(v));
    return lo + hi;
}
__device__ __forceinline__ ull pack2(float lo, float hi) {
    ull v;
    asm("mov.b64 %0, {%1,%2};" : "=l"(v) : "f"(lo), "f"(hi));
    return v;
}
__device__ __forceinline__ void unpack2(float& lo, float& hi, ull v) {
    asm("mov.b64 {%0,%1}, %2;" : "=f"(lo), "=f"(hi) : "l"(v));
}

// ---------------------------------------------------------------------------
// 0) no-op spacer (keeps the ncu capture slot on the GRU kernel)
// ---------------------------------------------------------------------------
__global__ void noop_kernel() {}

// ---------------------------------------------------------------------------
// 1) basket embedding (1 warp does the 128-wide mean pool, float4 gathers)
// ---------------------------------------------------------------------------
__global__ void __launch_bounds__(64)
embed_kernel(const int* __restrict__ x,
             const float* __restrict__ encode_w,
             const float* __restrict__ wchange_w) {
    int bt = blockIdx.x;
    const int* xr = x + (size_t)bt * (MI + 1);
    __shared__ int s_items[MI];
    __shared__ int s_flag;
    int tid = threadIdx.x;
    if (tid < MI) s_items[tid] = xr[tid];
    if (tid == MI) s_flag = xr[MI];
    __syncthreads();

    if (tid < 32) {
        float4 acc = make_float4(0.f, 0.f, 0.f, 0.f);
        int cnt = 0;
        #pragma unroll
        for (int i = 0; i < MI; i++) {
            int it = s_items[i];                // warp-uniform
            if (it != 0) {
                cnt++;
                float4 v = *(const float4*)(encode_w + (size_t)it * En + 4 * tid);
                acc.x += v.x; acc.y += v.y; acc.z += v.z; acc.w += v.w;
            }
        }
        float inv = 1.f / (float)(cnt > 0 ? cnt : 1);
        acc.x *= inv; acc.y *= inv; acc.z *= inv; acc.w *= inv;
        *(float4*)(g_seq + (size_t)bt * Dn + 4 * tid) = acc;
    } else if (tid < 48) {
        g_seq[(size_t)bt * Dn + En + (tid - 32)] = wchange_w[s_flag * 16 + (tid - 32)];
    }
}

// ---------------------------------------------------------------------------
// 2) C[M,N] = A[M,144]*Bm[N,144]^T + bias
//    64x64 tile, 128 threads, 8x4 micro-tile, two 72-k slabs
// ---------------------------------------------------------------------------
__global__ void __launch_bounds__(128)
gemm_tn(const float* __restrict__ A, const float* __restrict__ Bm,
        const float* __restrict__ bias, float* __restrict__ C, int N) {
    extern __shared__ float sm[];
    float* Ast = sm;              // [64][KP2]
    float* Bst = sm + 64 * KP2;   // [64][KP2]

    int tid = threadIdx.x;
    int m0 = blockIdx.y * 64, n0 = blockIdx.x * 64;
    int tx = tid & 15, ty = tid >> 4;

    ull acc[8][4];
    #pragma unroll
    for (int i = 0; i < 8; i++)
        #pragma unroll
        for (int j = 0; j < 4; j++) acc[i][j] = 0ull;

    for (int ks = 0; ks < 2; ks++) {
        int k0 = ks * KH;
        #pragma unroll
        for (int p = 0; p < 9; p++) {
            int idx = tid + p * 128;
            int r = idx / 18, c = idx - 18 * r;
            *(float4*)(Ast + r * KP2 + 4 * c) =
                *(const float4*)(A + (size_t)(m0 + r) * KD + k0 + 4 * c);
        }
        #pragma unroll
        for (int p = 0; p < 9; p++) {
            int idx = tid + p * 128;
            int r = idx / 18, c = idx - 18 * r;
            float4 v = make_float4(0.f, 0.f, 0.f, 0.f);
            if (n0 + r < N)
                v = *(const float4*)(Bm + (size_t)(n0 + r) * KD + k0 + 4 * c);
            *(float4*)(Bst + r * KP2 + 4 * c) = v;
        }
        __syncthreads();

        const float* aBase = Ast + (8 * ty) * KP2;
        const ulonglong2* bP[4];
        #pragma unroll
        for (int j = 0; j < 4; j++)
            bP[j] = (const ulonglong2*)(Bst + (tx + 16 * j) * KP2);

        #pragma unroll 6
        for (int kq = 0; kq < 18; kq++) {
            ulonglong2 b[4];
            #pragma unroll
            for (int j = 0; j < 4; j++) b[j] = bP[j][kq];
            #pragma unroll
            for (int i = 0; i < 8; i++) {
                ulonglong2 a = ((const ulonglong2*)(aBase + i * KP2))[kq];
                #pragma unroll
                for (int j = 0; j < 4; j++) {
                    fma2(acc[i][j], a.x, b[j].x);
                    fma2(acc[i][j], a.y, b[j].y);
                }
            }
        }
        __syncthreads();
    }

    #pragma unroll
    for (int j = 0; j < 4; j++) {
        int n = n0 + tx + 16 * j;
        if (n < N) {
            float bv = bias[n];
            #pragma unroll
            for (int i = 0; i < 8; i++) {
                int m = m0 + 8 * ty + i;
                C[(size_t)m * N + n] = hsum2(acc[i][j]) + bv;
            }
        }
    }
}

// ---------------------------------------------------------------------------
// 3) GRU recurrence: one CTA per batch, 216 threads, 2 gate-rows per thread,
//    ALL w_hh weights register-resident (144 ull pairs) -> zero smem weight
//    traffic per step. Rows 2j,2j+1; rows 0-143 r, 144-287 z, 288-431 n.
// ---------------------------------------------------------------------------
__global__ void __launch_bounds__(GTHR, 1)
gru_kernel(const float* __restrict__ w_hh, const float* __restrict__ b_hh,
           const float* __restrict__ hidden, float* __restrict__ out) {
    __shared__ __align__(16) float s_h[Dn];
    __shared__ float s_A[G3];
    __shared__ float s_gin[Dn];

    int b = blockIdx.x;
    int j = threadIdx.x;

    // load both weight rows into registers (contiguous: 144 pairs)
    const ull* wr = (const ull*)(w_hh + (size_t)(2 * j) * KD);
    ull wA[72], wB[72];
    #pragma unroll
    for (int p = 0; p < 72; p++) wA[p] = wr[p];
    #pragma unroll
    for (int p = 0; p < 72; p++) wB[p] = wr[72 + p];

    float bias0, bias1;
    unpack2(bias0, bias1, ((const ull*)b_hh)[j]);

    if (j < Dn) s_h[j] = hidden[(size_t)b * Dn + j];
    __syncthreads();

    const float* giB = g_gi + (size_t)b * Tn * G3;
    float* hsB       = g_hseq + (size_t)b * Tn * Dn;
    const ulonglong2* h2 = (const ulonglong2*)s_h;   // 36 quads

    ull gicur = ((const ull*)giB)[j];                 // prefetch t=0 (rows 2j,2j+1)

    for (int t = 0; t < Tn; t++) {
        ull a0 = pack2(bias0, 0.f), a1 = 0ull;        // row 2j
        ull c0 = pack2(bias1, 0.f), c1 = 0ull;        // row 2j+1

        // 2-group-deep pipelined broadcast loads of h (6-quad rotating buffer)
        ulonglong2 hb[6];
        #pragma unroll
        for (int q = 0; q < 6; q++) hb[q] = h2[q];

        #pragma unroll
        for (int g = 0; g < 12; g++) {
            int slot = (g & 1) * 3;
            ulonglong2 q0 = hb[slot], q1 = hb[slot + 1], q2 = hb[slot + 2];
            if (g < 10) {
                hb[slot]     = h2[3 * g + 6];
                hb[slot + 1] = h2[3 * g + 7];
                hb[slot + 2] = h2[3 * g + 8];
            }
            #pragma unroll
            for (int e = 0; e < 3; e++) {
                int q = 3 * g + e;
                ulonglong2 hq = (e == 0) ? q0 : (e == 1) ? q1 : q2;
                fma2(a0, wA[2 * q],     hq.x);
                fma2(a1, wA[2 * q + 1], hq.y);
                fma2(c0, wB[2 * q],     hq.x);
                fma2(c1, wB[2 * q + 1], hq.y);
            }
        }
        float A0 = hsum2(a0) + hsum2(a1);
        float A1 = hsum2(c0) + hsum2(c1);

        float g0, g1;
        unpack2(g0, g1, gicur);
        if (t + 1 < Tn) gicur = ((const ull*)(giB + (t + 1) * G3))[j];

        if (j < Dn) {                              // r or z rows (0..287)
            *(float2*)(s_A + 2 * j) = make_float2(g0 + A0, g1 + A1);
        } else {                                   // n rows (288..431)
            *(float2*)(s_A + 2 * j) = make_float2(A0, A1);
            *(float2*)(s_gin + 2 * j - 2 * Dn) = make_float2(g0, g1);   // FIXED
        }
        __syncthreads();

        if (j < Dn) {
            float r = 1.f / (1.f + __expf(-s_A[j]));
            float z = 1.f / (1.f + __expf(-s_A[j + Dn]));
            float e = __expf(-2.f * (s_gin[j] + r * s_A[j + 2 * Dn]));
            float n = 2.f / (1.f + e) - 1.f;       // tanh
            float hn = (1.f - z) * n + z * s_h[j];
            s_h[j] = hn;
            hsB[t * Dn + j] = hn;
        }
        __syncthreads();
    }

    if (j < Dn) out[(size_t)Bn * Tn * En + (size_t)b * Dn + j] = s_h[j];
}

// ---------------------------------------------------------------------------
extern "C" void kernel_launch(void* const* d_in, const int* in_sizes, int n_in,
                              void* d_out, int out_size) {
    const int*   x        = (const int*)  d_in[0];
    const float* hidden   = (const float*)d_in[2];
    const float* encode_w = (const float*)d_in[3];
    const float* wchange  = (const float*)d_in[4];
    const float* w_ih     = (const float*)d_in[5];
    const float* w_hh     = (const float*)d_in[6];
    const float* b_ih     = (const float*)d_in[7];
    const float* b_hh     = (const float*)d_in[8];
    const float* fc_w     = (const float*)d_in[9];
    const float* fc_b     = (const float*)d_in[10];
    float* out = (float*)d_out;

    float *p_seq, *p_gi, *p_hseq;
    cudaGetSymbolAddress((void**)&p_seq,  g_seq);
    cudaGetSymbolAddress((void**)&p_gi,   g_gi);
    cudaGetSymbolAddress((void**)&p_hseq, g_hseq);

    const int gemm_smem = 2 * 64 * KP2 * 4;                       // 38912 B

    // 1) embed
    embed_kernel<<<Bn * Tn, 64>>>(x, encode_w, wchange);

    // 2) gi = seq @ w_ih^T + b_ih   (6400 x 432)
    {
        dim3 grid((G3 + 63) / 64, (Bn * Tn) / 64);
        gemm_tn<<<grid, 128, gemm_smem>>>(p_seq, w_ih, b_ih, p_gi, G3);
    }

    // spacer so the ncu capture slot lands on the GRU kernel
    noop_kernel<<<1, 32>>>();

    // 3) GRU recurrence (one CTA per batch row), writes h_last to out tail
    gru_kernel<<<Bn, GTHR>>>(w_hh, b_hh, hidden, out);

    // 4) dynamic_user = hseq @ fc_w^T + fc_b  (6400 x 128) -> out head
    {
        dim3 grid(En / 64, (Bn * Tn) / 64);
        gemm_tn<<<grid, 128, gemm_smem>>>(p_hseq, fc_w, fc_b, out, En);
    }
}